// round 10
// baseline (speedup 1.0000x reference)
#include <cuda_runtime.h>
#include <cuda_bf16.h>
#include <cstdint>
#include <cstddef>

typedef unsigned long long u64;
typedef unsigned int u32;

#define NROWS  65536
#define LATENT 256
#define NNODES 256
#define TM     128
#define NTILES (NROWS / TM)   // 512
#define GRID   152
#define NT     640            // 16 compute warps + 4 store warps
#define NC     512
#define EPSF   1.1920929e-7f
#define MARGIN 0.08f
#define CAP    2048

// ---- smem layout (byte offsets from 1KB-aligned base) ----
#define BSM(c)   ((c) * 32768)            // 4 x 32KB persistent bf16 B tiles
#define AST(s)   (131072 + (s) * 16384)   // 2 x 16KB A stages
#define T_E2RAW  163840
#define T_E2D    164864
#define T_Z2P    165888
#define T_Z2RAW  167936
#define T_Z2PP   168448
#define T_RQM    168960
#define T_RQS    171008
#define T_QTHR   173056
#define T_RQSI   173568
#define T_KEY    174080
#define T_BMU    175104
#define T_CNT    175616
#define T_SLOT   175624
#define T_MBF    175632
#define T_MBE    175640
#define T_LIST   175648                   // 2048 * 4 = 8192
#define T_BMUP   183840
#define T_TAB    184352                   // 768 * 8 = 6144
#define SMEM_BYTES (190496 + 1024)

__device__ __forceinline__ u32 smaddr(const void* p) { return (u32)__cvta_generic_to_shared(p); }
__device__ __forceinline__ u32 toff(int row, int kbyte) {
    u32 o = (u32)(row * 128 + kbyte);
    return o ^ ((o >> 3) & 0x70);          // SW128
}
__device__ __forceinline__ void ldsm4(u32* r, u32 addr) {
    asm volatile("ldmatrix.sync.aligned.m8n8.x4.shared.b16 {%0,%1,%2,%3}, [%4];"
                 : "=r"(r[0]), "=r"(r[1]), "=r"(r[2]), "=r"(r[3]) : "r"(addr));
}
__device__ __forceinline__ void mma16816(float* d, const u32* a, u32 b0, u32 b1) {
    asm volatile("mma.sync.aligned.m16n8k16.row.col.f32.bf16.bf16.f32 "
                 "{%0,%1,%2,%3}, {%4,%5,%6,%7}, {%8,%9}, {%0,%1,%2,%3};"
                 : "+f"(d[0]), "+f"(d[1]), "+f"(d[2]), "+f"(d[3])
                 : "r"(a[0]), "r"(a[1]), "r"(a[2]), "r"(a[3]), "r"(b0), "r"(b1));
}
__device__ __forceinline__ u64 packf2(float lo, float hi) {
    u64 d; asm("mov.b64 %0, {%1, %2};" : "=l"(d) : "f"(lo), "f"(hi)); return d;
}
__device__ __forceinline__ void unpackf2(float& lo, float& hi, u64 v) {
    asm("mov.b64 {%0, %1}, %2;" : "=f"(lo), "=f"(hi) : "l"(v));
}
__device__ __forceinline__ u64 add2(u64 a, u64 b) {
    u64 d; asm("add.rn.f32x2 %0, %1, %2;" : "=l"(d) : "l"(a), "l"(b)); return d;
}
__device__ __forceinline__ u64 mul2(u64 a, u64 b) {
    u64 d; asm("mul.rn.f32x2 %0, %1, %2;" : "=l"(d) : "l"(a), "l"(b)); return d;
}
__device__ __forceinline__ u64 fma2(u64 a, u64 b, u64 c) {
    u64 d; asm("fma.rn.f32x2 %0, %1, %2, %3;" : "=l"(d) : "l"(a), "l"(b), "l"(c)); return d;
}

#define COMPBAR() asm volatile("bar.sync 1, 512;" ::: "memory")
#define STBAR()   asm volatile("bar.sync 2, 128;" ::: "memory")
#define MBAR_ARRIVE(mb) asm volatile("mbarrier.arrive.shared.b64 _, [%0];" :: "r"(mb) : "memory")
#define MBAR_WAIT(mb, par) do { \
    asm volatile("{\n\t.reg .pred P1;\n\t" \
        "W_%=:\n\t" \
        "mbarrier.try_wait.parity.acquire.cta.shared::cta.b64 P1, [%0], %1, 0x989680;\n\t" \
        "@P1 bra.uni D_%=;\n\t" \
        "bra.uni W_%=;\n\t" \
        "D_%=:\n\t}" :: "r"(mb), "r"(par) : "memory"); \
} while (0)

__global__ void __launch_bounds__(NT, 1)
som_main(const float* __restrict__ Z, const float* __restrict__ E,
         const int* __restrict__ Alpha, float* __restrict__ out)
{
    extern __shared__ char smraw[];
    char* SB = (char*)(((uintptr_t)smraw + 1023) & ~(uintptr_t)1023);
    float* e2raw = (float*)(SB + T_E2RAW);
    float* e2d   = (float*)(SB + T_E2D);
    float* z2p   = (float*)(SB + T_Z2P);
    float* z2raw = (float*)(SB + T_Z2RAW);
    float* z2pp  = (float*)(SB + T_Z2PP);
    float* rqm   = (float*)(SB + T_RQM);
    float* rqsum = (float*)(SB + T_RQS);
    float* qthr  = (float*)(SB + T_QTHR);
    float* rqs   = (float*)(SB + T_RQSI);
    u64*   keyA  = (u64*)(SB + T_KEY);
    int*   bmuS  = (int*)(SB + T_BMU);
    int*   cnt   = (int*)(SB + T_CNT);
    int*   slotR0= (int*)(SB + T_SLOT);
    u32*   list  = (u32*)(SB + T_LIST);
    int*   bmuP  = (int*)(SB + T_BMUP);
    u64*   tab   = (u64*)(SB + T_TAB);
    const u32 mbf = smaddr(SB + T_MBF);
    const u32 mbe = smaddr(SB + T_MBE);

    const int t = threadIdx.x, wid = t >> 5, lane = t & 31;

    // alpha (robust)
    int ai = Alpha[0];
    float aa = (ai > 0 && ai < 1000000) ? (float)ai : __int_as_float(ai);
    const float inva = 1.0f / aa;
    const float coef = -(aa + 1.0f) * 0.5f;
    const bool fast = (aa == 10.0f);
    const u64 cm2 = packf2(-2.f * inva, -2.f * inva);

    // ---- one-time init: persistent bf16 B tiles + e2 + mbarriers ----
    for (int v = t; v < 8192; v += NT) {     // 4 chunks x 256 nodes x 8 kgroups
        int ch = v >> 11, node = (v >> 3) & 255, kg = v & 7;
        const float* src = E + (size_t)node * LATENT + ch * 64 + kg * 8;
        float4 va = *(const float4*)(src), vb = *(const float4*)(src + 4);
        __nv_bfloat16 h[8];
        h[0]=__float2bfloat16(va.x); h[1]=__float2bfloat16(va.y);
        h[2]=__float2bfloat16(va.z); h[3]=__float2bfloat16(va.w);
        h[4]=__float2bfloat16(vb.x); h[5]=__float2bfloat16(vb.y);
        h[6]=__float2bfloat16(vb.z); h[7]=__float2bfloat16(vb.w);
        *(uint4*)(SB + BSM(ch) + toff(node, kg * 16)) = *(uint4*)h;
    }
    if (t < NNODES) {
        const float4* er = (const float4*)(E + (size_t)t * LATENT);
        float s = 0.f;
        #pragma unroll 8
        for (int i = 0; i < 64; i++) { float4 v = er[i]; s += v.x*v.x + v.y*v.y + v.z*v.z + v.w*v.w; }
        e2raw[t] = s;
        e2d[t]   = s * inva;
    }
    if (t == 0) {
        asm volatile("mbarrier.init.shared.b64 [%0], 1;" :: "r"(mbf) : "memory");
        asm volatile("mbarrier.init.shared.b64 [%0], 1;" :: "r"(mbe) : "memory");
    }
    __syncthreads();   // last full-CTA barrier before role split

    const size_t NBOFF  = (size_t)NROWS * 256;
    const size_t QOFF   = (size_t)NROWS * 1536;
    const size_t BMUOFF = (size_t)NROWS * 1792;

    if (wid < 16) {
        // ================= compute role (512 threads) =================
        const int g = lane >> 2, qd = lane & 3;
        const int wr = (wid >> 2) * 32, wc = (wid & 3) * 64;
        const int arow = t >> 2, akp = t & 3;
        int ph_e = 1;   // producer phase: first wait-empty passes immediately

        for (int tl = blockIdx.x; tl < NTILES; tl += GRID) {
            const int R0 = tl * TM;
            if (t < TM) keyA[t] = ~0ull;
            if (t == 0) *cnt = 0;

            float acc[2][8][4];
            #pragma unroll
            for (int mt = 0; mt < 2; mt++)
                #pragma unroll
                for (int j = 0; j < 8; j++)
                    #pragma unroll
                    for (int c4 = 0; c4 < 4; c4++) acc[mt][j][c4] = 0.f;
            float z2acc = 0.f;

            // build A chunk 0 -> stage 0
            {
                const float4* zsrc = (const float4*)(Z + (size_t)(R0 + arow) * LATENT + akp * 16);
                #pragma unroll
                for (int gb = 0; gb < 2; gb++) {
                    float4 va = zsrc[2*gb], vb = zsrc[2*gb + 1];
                    __nv_bfloat16 h[8];
                    z2acc = fmaf(va.x,va.x,fmaf(va.y,va.y,fmaf(va.z,va.z,fmaf(va.w,va.w,z2acc))));
                    z2acc = fmaf(vb.x,vb.x,fmaf(vb.y,vb.y,fmaf(vb.z,vb.z,fmaf(vb.w,vb.w,z2acc))));
                    h[0]=__float2bfloat16(va.x); h[1]=__float2bfloat16(va.y);
                    h[2]=__float2bfloat16(va.z); h[3]=__float2bfloat16(va.w);
                    h[4]=__float2bfloat16(vb.x); h[5]=__float2bfloat16(vb.y);
                    h[6]=__float2bfloat16(vb.z); h[7]=__float2bfloat16(vb.w);
                    *(uint4*)(SB + AST(0) + toff(arow, akp * 32 + gb * 16)) = *(uint4*)h;
                }
            }
            for (int c = 0; c < 4; c++) {
                COMPBAR();   // stage c&1 ready; stage (c+1)&1 free
                if (c < 3) {
                    const float4* zsrc = (const float4*)(Z + (size_t)(R0 + arow) * LATENT + (c + 1) * 64 + akp * 16);
                    #pragma unroll
                    for (int gb = 0; gb < 2; gb++) {
                        float4 va = zsrc[2*gb], vb = zsrc[2*gb + 1];
                        __nv_bfloat16 h[8];
                        z2acc = fmaf(va.x,va.x,fmaf(va.y,va.y,fmaf(va.z,va.z,fmaf(va.w,va.w,z2acc))));
                        z2acc = fmaf(vb.x,vb.x,fmaf(vb.y,vb.y,fmaf(vb.z,vb.z,fmaf(vb.w,vb.w,z2acc))));
                        h[0]=__float2bfloat16(va.x); h[1]=__float2bfloat16(va.y);
                        h[2]=__float2bfloat16(va.z); h[3]=__float2bfloat16(va.w);
                        h[4]=__float2bfloat16(vb.x); h[5]=__float2bfloat16(vb.y);
                        h[6]=__float2bfloat16(vb.z); h[7]=__float2bfloat16(vb.w);
                        *(uint4*)(SB + AST((c + 1) & 1) + toff(arow, akp * 32 + gb * 16)) = *(uint4*)h;
                    }
                }
                const u32 sAa = smaddr(SB + AST(c & 1));
                const u32 sBa = smaddr(SB + BSM(c));
                const int la = lane & 15, kh = lane >> 4;
                #pragma unroll
                for (int ks = 0; ks < 4; ks++) {
                    const int kb = ks * 32 + kh * 16;
                    u32 af[2][4];
                    ldsm4(af[0], sAa + toff(wr + la, kb));
                    ldsm4(af[1], sAa + toff(wr + 16 + la, kb));
                    u32 bf[4][4];
                    #pragma unroll
                    for (int p = 0; p < 4; p++)
                        ldsm4(bf[p], sBa + toff(wc + p * 16 + la, kb));
                    #pragma unroll
                    for (int mt = 0; mt < 2; mt++)
                        #pragma unroll
                        for (int j = 0; j < 8; j++)
                            mma16816(acc[mt][j], af[mt], bf[j >> 1][j & 1], bf[j >> 1][(j & 1) + 2]);
                }
            }
            // z2
            z2p[arow * 4 + akp] = z2acc;
            COMPBAR();
            if (t < TM) {
                float z = z2p[4*t] + z2p[4*t+1] + z2p[4*t+2] + z2p[4*t+3];
                z2raw[t] = z;
                z2pp[t]  = fmaf(z, inva, 1.0f);
            }
            COMPBAR();

            // q eval
            u64 ed2[8];
            #pragma unroll
            for (int j = 0; j < 8; j++) ed2[j] = *(const u64*)(e2d + wc + j * 8 + 2 * qd);
            float qmaxr[4], qsumr[4];
            #pragma unroll
            for (int mt = 0; mt < 2; mt++) {
                #pragma unroll
                for (int hf = 0; hf < 2; hf++) {
                    const int row = wr + mt * 16 + hf * 8 + g;
                    const u64 zp = packf2(z2pp[row], z2pp[row]);
                    u64 qs2 = 0ull;
                    float qmax = 0.f;
                    #pragma unroll
                    for (int j = 0; j < 8; j++) {
                        u64 a2 = packf2(acc[mt][j][2*hf], acc[mt][j][2*hf+1]);
                        u64 p  = fma2(a2, cm2, add2(zp, ed2[j]));
                        float q0, q1;
                        if (fast) {
                            u64 x2 = mul2(p, p);
                            u64 x4 = mul2(x2, x2);
                            u64 x8 = mul2(x4, x4);
                            u64 x11 = mul2(mul2(x8, x2), p);
                            float lo, hi; unpackf2(lo, hi, x11);
                            q0 = rsqrtf(lo); q1 = rsqrtf(hi);
                        } else {
                            float lo, hi; unpackf2(lo, hi, p);
                            q0 = exp2f(coef * __log2f(lo));
                            q1 = exp2f(coef * __log2f(hi));
                        }
                        qs2 = add2(qs2, packf2(q0, q1));
                        qmax = fmaxf(qmax, fmaxf(q0, q1));
                        acc[mt][j][2*hf] = q0;
                        acc[mt][j][2*hf+1] = q1;
                    }
                    float slo, shi; unpackf2(slo, shi, qs2);
                    qmaxr[mt*2+hf] = qmax;
                    qsumr[mt*2+hf] = slo + shi;
                }
            }
            #pragma unroll
            for (int i = 0; i < 4; i++) {
                qmaxr[i] = fmaxf(qmaxr[i], __shfl_xor_sync(0xffffffffu, qmaxr[i], 1));
                qmaxr[i] = fmaxf(qmaxr[i], __shfl_xor_sync(0xffffffffu, qmaxr[i], 2));
                qsumr[i] += __shfl_xor_sync(0xffffffffu, qsumr[i], 1);
                qsumr[i] += __shfl_xor_sync(0xffffffffu, qsumr[i], 2);
            }
            if (qd == 0) {
                #pragma unroll
                for (int i = 0; i < 4; i++) {
                    const int row = wr + (i >> 1) * 16 + (i & 1) * 8 + g;
                    rqm[row * 4 + (wid & 3)]   = qmaxr[i];
                    rqsum[row * 4 + (wid & 3)] = qsumr[i];
                }
            }
            COMPBAR();
            if (t < TM) {
                float qm = 0.f, s = 0.f;
                #pragma unroll
                for (int k = 0; k < 4; k++) { qm = fmaxf(qm, rqm[t*4+k]); s += rqsum[t*4+k]; }
                rqs[t] = 1.0f / s;
                float pmin = exp2f(__log2f(qm) / coef);
                float y = pmin + MARGIN * inva;
                float qt;
                if (fast) {
                    float y2 = y*y, y4 = y2*y2, y8 = y4*y4;
                    qt = rsqrtf(y8 * y2 * y);
                } else {
                    qt = exp2f(coef * __log2f(y));
                }
                qthr[t] = qt;
            }
            COMPBAR();

            // candidate collection
            #pragma unroll
            for (int mt = 0; mt < 2; mt++)
                #pragma unroll
                for (int hf = 0; hf < 2; hf++) {
                    const int row = wr + mt * 16 + hf * 8 + g;
                    const float th = qthr[row];
                    #pragma unroll
                    for (int j = 0; j < 8; j++)
                        #pragma unroll
                        for (int u2 = 0; u2 < 2; u2++) {
                            if (acc[mt][j][2*hf+u2] >= th) {
                                int idx = atomicAdd(cnt, 1);
                                if (idx < CAP)
                                    list[idx] = ((u32)row << 8) | (u32)(wc + j * 8 + 2 * qd + u2);
                            }
                        }
                }
            COMPBAR();

            // exact fp32 refinement
            {
                const int n = min(*cnt, CAP);
                for (int e = wid; e < n; e += 16) {
                    u32 ent = list[e];
                    int row = ent >> 8, node = ent & 255;
                    const float4* zr = (const float4*)(Z + (size_t)(R0 + row) * LATENT);
                    const float4* er = (const float4*)(E + (size_t)node * LATENT);
                    float4 za = zr[lane*2], zb = zr[lane*2+1];
                    float4 ea = er[lane*2], eb = er[lane*2+1];
                    float d = za.x*ea.x + za.y*ea.y + za.z*ea.z + za.w*ea.w
                            + zb.x*eb.x + zb.y*eb.y + zb.z*eb.z + zb.w*eb.w;
                    #pragma unroll
                    for (int o = 16; o > 0; o >>= 1) d += __shfl_down_sync(0xffffffffu, d, o);
                    if (lane == 0) {
                        float dex = fmaxf(z2raw[row] + e2raw[node] - 2.f * d, 0.f);
                        u64 key = ((u64)__float_as_uint(dex) << 32) | (u64)node;
                        atomicMin(&keyA[row], key);
                    }
                }
            }
            COMPBAR();

            // ---- handoff to store warps ----
            if (t == 0) MBAR_WAIT(mbe, ph_e);   // slot free
            COMPBAR();
            if (t < TM) {
                int b = (int)(keyA[t] & 0xffffffffu);
                bmuS[t] = b;
                out[BMUOFF + R0 + t] = (float)b;
            }
            if (t == 0) *slotR0 = R0;
            COMPBAR();
            if (t == 0) MBAR_ARRIVE(mbf);
            ph_e ^= 1;

            // ---- q stores (overlap store-warps' copies) ----
            #pragma unroll
            for (int mt = 0; mt < 2; mt++)
                #pragma unroll
                for (int hf = 0; hf < 2; hf++) {
                    const int row = wr + mt * 16 + hf * 8 + g;
                    const float rq = rqs[row];
                    #pragma unroll
                    for (int j = 0; j < 8; j++) {
                        float2 qv;
                        qv.x = fmaf(acc[mt][j][2*hf],   rq, EPSF);
                        qv.y = fmaf(acc[mt][j][2*hf+1], rq, EPSF);
                        *(float2*)(out + QOFF + (size_t)(R0 + row) * NNODES + wc + j * 8 + 2 * qd) = qv;
                    }
                }
        }
        // sentinel: terminate store warps
        if (t == 0) {
            MBAR_WAIT(mbe, ph_e);
            *slotR0 = -1;
            MBAR_ARRIVE(mbf);
        }
    } else {
        // ================= store role (128 threads) =================
        const int stid = t - NC;
        int ph_f = 0;
        while (true) {
            MBAR_WAIT(mbf, ph_f);
            ph_f ^= 1;
            const int R0s = *slotR0;
            int myb = bmuS[stid];
            STBAR();                     // all threads have read the slot
            if (R0s < 0) break;
            if (stid == 0) MBAR_ARRIVE(mbe);   // free the slot for the producer
            bmuP[stid] = myb;
            STBAR();
            // build copy table: 6 copies per row
            for (int v = stid; v < TM * 6; v += 128) {
                int row2 = v / 6, s = v - row2 * 6;
                int b = bmuP[row2];
                int idx;
                if (s <= 1) {
                    idx = b;
                } else {
                    int k1 = b >> 4, k2 = b & 15;
                    if      (s == 2) idx = (((k1 + 15) & 15) << 4) + k2;   // up
                    else if (s == 3) idx = (((k1 + 1)  & 15) << 4) + k2;   // down
                    else if (s == 4) idx = (k1 << 4) + ((k2 + 1)  & 15);   // right
                    else             idx = (k1 << 4) + ((k2 + 15) & 15);   // left
                }
                u64 dstoff = (s == 0)
                    ? (u64)(R0s + row2) * LATENT
                    : (u64)NBOFF + ((u64)(R0s + row2) * 5 + (s - 1)) * LATENT;
                tab[v] = (dstoff << 8) | (u64)(u32)idx;
            }
            STBAR();
            // flat coalesced copy: 768 copies x 64 float4
            #pragma unroll 8
            for (int i = 0; i < (TM * 6 * 64) / 128; i++) {
                int v = i * 128 + stid;
                int copy = v >> 6, seg = v & 63;
                u64 pk = tab[copy];
                int idx = (int)(pk & 0xff);
                u64 dstoff = pk >> 8;
                float4 val = ((const float4*)(E + (size_t)idx * LATENT))[seg];
                ((float4*)(out + dstoff))[seg] = val;
            }
        }
    }
}

extern "C" void kernel_launch(void* const* d_in, const int* in_sizes, int n_in,
                              void* d_out, int out_size) {
    const float* Z = (const float*)d_in[0];
    const float* E = (const float*)d_in[1];
    const int*   A = (const int*)d_in[2];
    float* out = (float*)d_out;

    cudaFuncSetAttribute(som_main, cudaFuncAttributeMaxDynamicSharedMemorySize, SMEM_BYTES);
    som_main<<<GRID, NT, SMEM_BYTES>>>(Z, E, A, out);
}

// round 11
// speedup vs baseline: 1.7155x; 1.7155x over previous
#include <cuda_runtime.h>
#include <cuda_bf16.h>
#include <cstdint>
#include <cstddef>

typedef unsigned long long u64;
typedef unsigned int u32;

#define NROWS  65536
#define LATENT 256
#define NNODES 256
#define TM     128
#define NT     512
#define GRID   256            // 2 tiles per CTA
#define EPSF   1.1920929e-7f
#define MARGIN 0.08f
#define CAP    2048

// ---- smem layout (byte offsets from 1KB-aligned base) ----
#define BSM(c)   ((c) * 32768)             // 4 x 32KB persistent bf16 B tiles
#define AST(s)   (131072 + (s) * 16384)    // 2 x 16KB A stages
#define T_LIST   131072                    // overlays A stages (dead in that phase)
#define T_E2RAW  163840
#define T_E2D    164864
#define T_Z2P    165888
#define T_Z2RAW  167936
#define T_Z2PP   168448
#define T_RQM    168960
#define T_RQS    171008
#define T_QTHR   173056
#define T_RQSI   173568
#define T_KEY    174080
#define T_BMU    175104
#define T_CNT    175616
#define T_TAB    175632                    // 768 * 8 = 6144
#define SMEM_BYTES (181776 + 1024)

__device__ __forceinline__ u32 smaddr(const void* p) { return (u32)__cvta_generic_to_shared(p); }
__device__ __forceinline__ u32 toff(int row, int kbyte) {
    u32 o = (u32)(row * 128 + kbyte);
    return o ^ ((o >> 3) & 0x70);          // SW128
}
__device__ __forceinline__ void ldsm4(u32* r, u32 addr) {
    asm volatile("ldmatrix.sync.aligned.m8n8.x4.shared.b16 {%0,%1,%2,%3}, [%4];"
                 : "=r"(r[0]), "=r"(r[1]), "=r"(r[2]), "=r"(r[3]) : "r"(addr));
}
__device__ __forceinline__ void mma16816(float* d, const u32* a, u32 b0, u32 b1) {
    asm volatile("mma.sync.aligned.m16n8k16.row.col.f32.bf16.bf16.f32 "
                 "{%0,%1,%2,%3}, {%4,%5,%6,%7}, {%8,%9}, {%0,%1,%2,%3};"
                 : "+f"(d[0]), "+f"(d[1]), "+f"(d[2]), "+f"(d[3])
                 : "r"(a[0]), "r"(a[1]), "r"(a[2]), "r"(a[3]), "r"(b0), "r"(b1));
}
__device__ __forceinline__ u64 packf2(float lo, float hi) {
    u64 d; asm("mov.b64 %0, {%1, %2};" : "=l"(d) : "f"(lo), "f"(hi)); return d;
}
__device__ __forceinline__ void unpackf2(float& lo, float& hi, u64 v) {
    asm("mov.b64 {%0, %1}, %2;" : "=f"(lo), "=f"(hi) : "l"(v));
}
__device__ __forceinline__ u64 add2(u64 a, u64 b) {
    u64 d; asm("add.rn.f32x2 %0, %1, %2;" : "=l"(d) : "l"(a), "l"(b)); return d;
}
__device__ __forceinline__ u64 mul2(u64 a, u64 b) {
    u64 d; asm("mul.rn.f32x2 %0, %1, %2;" : "=l"(d) : "l"(a), "l"(b)); return d;
}
__device__ __forceinline__ u64 fma2(u64 a, u64 b, u64 c) {
    u64 d; asm("fma.rn.f32x2 %0, %1, %2, %3;" : "=l"(d) : "l"(a), "l"(b), "l"(c)); return d;
}

__global__ void __launch_bounds__(NT, 1)
som_main(const float* __restrict__ Z, const float* __restrict__ E,
         const int* __restrict__ Alpha, float* __restrict__ out)
{
    extern __shared__ char smraw[];
    char* SB = (char*)(((uintptr_t)smraw + 1023) & ~(uintptr_t)1023);
    float* e2raw = (float*)(SB + T_E2RAW);
    float* e2d   = (float*)(SB + T_E2D);
    float* z2p   = (float*)(SB + T_Z2P);
    float* z2raw = (float*)(SB + T_Z2RAW);
    float* z2pp  = (float*)(SB + T_Z2PP);
    float* rqm   = (float*)(SB + T_RQM);
    float* rqsum = (float*)(SB + T_RQS);
    float* qthr  = (float*)(SB + T_QTHR);
    float* rqs   = (float*)(SB + T_RQSI);
    u64*   keyA  = (u64*)(SB + T_KEY);
    int*   bmuS  = (int*)(SB + T_BMU);
    int*   cnt   = (int*)(SB + T_CNT);
    u64*   tab   = (u64*)(SB + T_TAB);
    u32*   list  = (u32*)(SB + T_LIST);

    const int t = threadIdx.x, wid = t >> 5, lane = t & 31;
    const int g = lane >> 2, qd = lane & 3;
    const int wr = (wid >> 2) * 32, wc = (wid & 3) * 64;
    const int arow = t >> 2, akp = t & 3;

    // alpha (robust)
    int ai = Alpha[0];
    float aa = (ai > 0 && ai < 1000000) ? (float)ai : __int_as_float(ai);
    const float inva = 1.0f / aa;
    const float coef = -(aa + 1.0f) * 0.5f;
    const bool fast = (aa == 10.0f);
    const u64 cm2 = packf2(-2.f * inva, -2.f * inva);

    // ---- one-time per CTA: persistent bf16 B tiles + e2 (E is L2-resident) ----
    for (int v = t; v < 8192; v += NT) {     // 4 chunks x 256 nodes x 8 kgroups
        int ch = v >> 11, node = (v >> 3) & 255, kg = v & 7;
        const float* src = E + (size_t)node * LATENT + ch * 64 + kg * 8;
        float4 va = *(const float4*)(src), vb = *(const float4*)(src + 4);
        __nv_bfloat16 h[8];
        h[0]=__float2bfloat16(va.x); h[1]=__float2bfloat16(va.y);
        h[2]=__float2bfloat16(va.z); h[3]=__float2bfloat16(va.w);
        h[4]=__float2bfloat16(vb.x); h[5]=__float2bfloat16(vb.y);
        h[6]=__float2bfloat16(vb.z); h[7]=__float2bfloat16(vb.w);
        *(uint4*)(SB + BSM(ch) + toff(node, kg * 16)) = *(uint4*)h;
    }
    if (t < NNODES) {
        const float4* er = (const float4*)(E + (size_t)t * LATENT);
        float s = 0.f;
        #pragma unroll 8
        for (int i = 0; i < 64; i++) { float4 v = er[i]; s += v.x*v.x + v.y*v.y + v.z*v.z + v.w*v.w; }
        e2raw[t] = s;
        e2d[t]   = s * inva;
    }
    __syncthreads();

    const size_t NBOFF  = (size_t)NROWS * 256;
    const size_t QOFF   = (size_t)NROWS * 1536;
    const size_t BMUOFF = (size_t)NROWS * 1792;

    for (int ti = 0; ti < 2; ti++) {
        const int R0 = (2 * blockIdx.x + ti) * TM;
        if (t < TM) keyA[t] = ~0ull;
        if (t == 0) *cnt = 0;

        float acc[2][8][4];
        #pragma unroll
        for (int mt = 0; mt < 2; mt++)
            #pragma unroll
            for (int j = 0; j < 8; j++)
                #pragma unroll
                for (int c4 = 0; c4 < 4; c4++) acc[mt][j][c4] = 0.f;
        float z2acc = 0.f;

        // build A chunk 0 -> stage 0
        {
            const float4* zsrc = (const float4*)(Z + (size_t)(R0 + arow) * LATENT + akp * 16);
            #pragma unroll
            for (int gb = 0; gb < 2; gb++) {
                float4 va = zsrc[2*gb], vb = zsrc[2*gb + 1];
                __nv_bfloat16 h[8];
                z2acc = fmaf(va.x,va.x,fmaf(va.y,va.y,fmaf(va.z,va.z,fmaf(va.w,va.w,z2acc))));
                z2acc = fmaf(vb.x,vb.x,fmaf(vb.y,vb.y,fmaf(vb.z,vb.z,fmaf(vb.w,vb.w,z2acc))));
                h[0]=__float2bfloat16(va.x); h[1]=__float2bfloat16(va.y);
                h[2]=__float2bfloat16(va.z); h[3]=__float2bfloat16(va.w);
                h[4]=__float2bfloat16(vb.x); h[5]=__float2bfloat16(vb.y);
                h[6]=__float2bfloat16(vb.z); h[7]=__float2bfloat16(vb.w);
                *(uint4*)(SB + AST(0) + toff(arow, akp * 32 + gb * 16)) = *(uint4*)h;
            }
        }
        for (int c = 0; c < 4; c++) {
            __syncthreads();   // stage c&1 visible; all warps done with stage (c+1)&1
            if (c < 3) {
                const float4* zsrc = (const float4*)(Z + (size_t)(R0 + arow) * LATENT + (c + 1) * 64 + akp * 16);
                #pragma unroll
                for (int gb = 0; gb < 2; gb++) {
                    float4 va = zsrc[2*gb], vb = zsrc[2*gb + 1];
                    __nv_bfloat16 h[8];
                    z2acc = fmaf(va.x,va.x,fmaf(va.y,va.y,fmaf(va.z,va.z,fmaf(va.w,va.w,z2acc))));
                    z2acc = fmaf(vb.x,vb.x,fmaf(vb.y,vb.y,fmaf(vb.z,vb.z,fmaf(vb.w,vb.w,z2acc))));
                    h[0]=__float2bfloat16(va.x); h[1]=__float2bfloat16(va.y);
                    h[2]=__float2bfloat16(va.z); h[3]=__float2bfloat16(va.w);
                    h[4]=__float2bfloat16(vb.x); h[5]=__float2bfloat16(vb.y);
                    h[6]=__float2bfloat16(vb.z); h[7]=__float2bfloat16(vb.w);
                    *(uint4*)(SB + AST((c + 1) & 1) + toff(arow, akp * 32 + gb * 16)) = *(uint4*)h;
                }
            }
            // deferred copies of the PREVIOUS tile, interleaved into this GEMM chunk
            if (ti == 1) {
                #pragma unroll
                for (int bb = 0; bb < 6; bb++) {
                    float4 vv[4]; u64 doff[4];
                    #pragma unroll
                    for (int i = 0; i < 4; i++) {
                        int item = (c * 24 + bb * 4 + i) * NT + t;
                        u64 pk = tab[item >> 6];
                        int idx = (int)(pk & 0xff);
                        int seg = item & 63;
                        doff[i] = (pk >> 8) + (u64)(seg * 4);
                        vv[i] = ((const float4*)(E + (size_t)idx * LATENT))[seg];
                    }
                    #pragma unroll
                    for (int i = 0; i < 4; i++)
                        *(float4*)(out + doff[i]) = vv[i];
                }
            }
            // mma on stage c&1 against persistent B chunk c
            const u32 sAa = smaddr(SB + AST(c & 1));
            const u32 sBa = smaddr(SB + BSM(c));
            const int la = lane & 15, kh = lane >> 4;
            #pragma unroll
            for (int ks = 0; ks < 4; ks++) {
                const int kb = ks * 32 + kh * 16;
                u32 af[2][4];
                ldsm4(af[0], sAa + toff(wr + la, kb));
                ldsm4(af[1], sAa + toff(wr + 16 + la, kb));
                u32 bf[4][4];
                #pragma unroll
                for (int p = 0; p < 4; p++)
                    ldsm4(bf[p], sBa + toff(wc + p * 16 + la, kb));
                #pragma unroll
                for (int mt = 0; mt < 2; mt++)
                    #pragma unroll
                    for (int j = 0; j < 8; j++)
                        mma16816(acc[mt][j], af[mt], bf[j >> 1][j & 1], bf[j >> 1][(j & 1) + 2]);
            }
        }
        // z2 finalize
        z2p[arow * 4 + akp] = z2acc;
        __syncthreads();
        if (t < TM) {
            float z = z2p[4*t] + z2p[4*t+1] + z2p[4*t+2] + z2p[4*t+3];
            z2raw[t] = z;
            z2pp[t]  = fmaf(z, inva, 1.0f);
        }
        __syncthreads();

        // q eval
        u64 ed2[8];
        #pragma unroll
        for (int j = 0; j < 8; j++) ed2[j] = *(const u64*)(e2d + wc + j * 8 + 2 * qd);
        float qmaxr[4], qsumr[4];
        #pragma unroll
        for (int mt = 0; mt < 2; mt++) {
            #pragma unroll
            for (int hf = 0; hf < 2; hf++) {
                const int row = wr + mt * 16 + hf * 8 + g;
                const u64 zp = packf2(z2pp[row], z2pp[row]);
                u64 qs2 = 0ull;
                float qmax = 0.f;
                #pragma unroll
                for (int j = 0; j < 8; j++) {
                    u64 a2 = packf2(acc[mt][j][2*hf], acc[mt][j][2*hf+1]);
                    u64 p  = fma2(a2, cm2, add2(zp, ed2[j]));   // p = 1 + d/alpha
                    float q0, q1;
                    if (fast) {
                        u64 x2 = mul2(p, p);
                        u64 x4 = mul2(x2, x2);
                        u64 x8 = mul2(x4, x4);
                        u64 x11 = mul2(mul2(x8, x2), p);
                        float lo, hi; unpackf2(lo, hi, x11);
                        q0 = rsqrtf(lo); q1 = rsqrtf(hi);
                    } else {
                        float lo, hi; unpackf2(lo, hi, p);
                        q0 = exp2f(coef * __log2f(lo));
                        q1 = exp2f(coef * __log2f(hi));
                    }
                    qs2 = add2(qs2, packf2(q0, q1));
                    qmax = fmaxf(qmax, fmaxf(q0, q1));
                    acc[mt][j][2*hf] = q0;
                    acc[mt][j][2*hf+1] = q1;
                }
                float slo, shi; unpackf2(slo, shi, qs2);
                qmaxr[mt*2+hf] = qmax;
                qsumr[mt*2+hf] = slo + shi;
            }
        }
        #pragma unroll
        for (int i = 0; i < 4; i++) {
            qmaxr[i] = fmaxf(qmaxr[i], __shfl_xor_sync(0xffffffffu, qmaxr[i], 1));
            qmaxr[i] = fmaxf(qmaxr[i], __shfl_xor_sync(0xffffffffu, qmaxr[i], 2));
            qsumr[i] += __shfl_xor_sync(0xffffffffu, qsumr[i], 1);
            qsumr[i] += __shfl_xor_sync(0xffffffffu, qsumr[i], 2);
        }
        if (qd == 0) {
            #pragma unroll
            for (int i = 0; i < 4; i++) {
                const int row = wr + (i >> 1) * 16 + (i & 1) * 8 + g;
                rqm[row * 4 + (wid & 3)]   = qmaxr[i];
                rqsum[row * 4 + (wid & 3)] = qsumr[i];
            }
        }
        __syncthreads();
        if (t < TM) {
            float qm = 0.f, s = 0.f;
            #pragma unroll
            for (int k = 0; k < 4; k++) { qm = fmaxf(qm, rqm[t*4+k]); s += rqsum[t*4+k]; }
            rqs[t] = 1.0f / s;
            float pmin = exp2f(__log2f(qm) / coef);
            float y = pmin + MARGIN * inva;
            float qt;
            if (fast) {
                float y2 = y*y, y4 = y2*y2, y8 = y4*y4;
                qt = rsqrtf(y8 * y2 * y);
            } else {
                qt = exp2f(coef * __log2f(y));
            }
            qthr[t] = qt;
        }
        __syncthreads();

        // q stores first (early DRAM)
        #pragma unroll
        for (int mt = 0; mt < 2; mt++)
            #pragma unroll
            for (int hf = 0; hf < 2; hf++) {
                const int row = wr + mt * 16 + hf * 8 + g;
                const float rq = rqs[row];
                #pragma unroll
                for (int j = 0; j < 8; j++) {
                    float2 qv;
                    qv.x = fmaf(acc[mt][j][2*hf],   rq, EPSF);
                    qv.y = fmaf(acc[mt][j][2*hf+1], rq, EPSF);
                    *(float2*)(out + QOFF + (size_t)(R0 + row) * NNODES + wc + j * 8 + 2 * qd) = qv;
                }
            }

        // candidate collection (list overlays dead A stages)
        #pragma unroll
        for (int mt = 0; mt < 2; mt++)
            #pragma unroll
            for (int hf = 0; hf < 2; hf++) {
                const int row = wr + mt * 16 + hf * 8 + g;
                const float th = qthr[row];
                #pragma unroll
                for (int j = 0; j < 8; j++)
                    #pragma unroll
                    for (int u2 = 0; u2 < 2; u2++) {
                        if (acc[mt][j][2*hf+u2] >= th) {
                            int idx = atomicAdd(cnt, 1);
                            if (idx < CAP)
                                list[idx] = ((u32)row << 8) | (u32)(wc + j * 8 + 2 * qd + u2);
                        }
                    }
            }
        __syncthreads();

        // exact fp32 refinement
        {
            const int n = min(*cnt, CAP);
            for (int e = wid; e < n; e += 16) {
                u32 ent = list[e];
                int row = ent >> 8, node = ent & 255;
                const float4* zr = (const float4*)(Z + (size_t)(R0 + row) * LATENT);
                const float4* er = (const float4*)(E + (size_t)node * LATENT);
                float4 za = zr[lane*2], zb = zr[lane*2+1];
                float4 ea = er[lane*2], eb = er[lane*2+1];
                float d = za.x*ea.x + za.y*ea.y + za.z*ea.z + za.w*ea.w
                        + zb.x*eb.x + zb.y*eb.y + zb.z*eb.z + zb.w*eb.w;
                #pragma unroll
                for (int o = 16; o > 0; o >>= 1) d += __shfl_down_sync(0xffffffffu, d, o);
                if (lane == 0) {
                    float dex = fmaxf(z2raw[row] + e2raw[node] - 2.f * d, 0.f);
                    u64 key = ((u64)__float_as_uint(dex) << 32) | (u64)node;
                    atomicMin(&keyA[row], key);
                }
            }
        }
        __syncthreads();
        if (t < TM) {
            int b = (int)(keyA[t] & 0xffffffffu);
            bmuS[t] = b;
            out[BMUOFF + R0 + t] = (float)b;
        }
        __syncthreads();

        // build copy table for THIS tile (consumed next tile's GEMM, or below if last)
        for (int v = t; v < TM * 6; v += NT) {
            int row2 = v / 6, s = v - row2 * 6;
            int b = bmuS[row2];
            int idx;
            if (s <= 1) {
                idx = b;
            } else {
                int k1 = b >> 4, k2 = b & 15;
                if      (s == 2) idx = (((k1 + 15) & 15) << 4) + k2;   // up
                else if (s == 3) idx = (((k1 + 1)  & 15) << 4) + k2;   // down
                else if (s == 4) idx = (k1 << 4) + ((k2 + 1)  & 15);   // right
                else             idx = (k1 << 4) + ((k2 + 15) & 15);   // left
            }
            u64 dstoff = (s == 0)
                ? (u64)(R0 + row2) * LATENT
                : (u64)NBOFF + ((u64)(R0 + row2) * 5 + (s - 1)) * LATENT;
            tab[v] = (dstoff << 8) | (u64)(u32)idx;
        }
        __syncthreads();

        if (ti == 1) {
            // last tile: copies not overlapped
            #pragma unroll 4
            for (int i = 0; i < (TM * 6 * 64) / NT; i++) {
                int v = i * NT + t;
                u64 pk = tab[v >> 6];
                int idx = (int)(pk & 0xff);
                int seg = v & 63;
                float4 val = ((const float4*)(E + (size_t)idx * LATENT))[seg];
                *(float4*)(out + (pk >> 8) + (u64)(seg * 4)) = val;
            }
        }
    }
}

extern "C" void kernel_launch(void* const* d_in, const int* in_sizes, int n_in,
                              void* d_out, int out_size) {
    const float* Z = (const float*)d_in[0];
    const float* E = (const float*)d_in[1];
    const int*   A = (const int*)d_in[2];
    float* out = (float*)d_out;

    cudaFuncSetAttribute(som_main, cudaFuncAttributeMaxDynamicSharedMemorySize, SMEM_BYTES);
    som_main<<<GRID, NT, SMEM_BYTES>>>(Z, E, A, out);
}